// round 1
// baseline (speedup 1.0000x reference)
#include <cuda_runtime.h>
#include <cstdint>
#include <cstddef>

// Problem constants (fixed by the dataset)
constexpr int Gn = 16;
constexpr int Bn = 8192;
constexpr int Kn = 1024;
constexpr int Dn = 64;

constexpr int TM = 64;   // rows of x per CTA
constexpr int TN = 64;   // centroids per CTA

__device__ __forceinline__ float fsqrt_approx(float v) {
    float r;
    asm("sqrt.approx.f32 %0, %1;" : "=f"(r) : "f"(v));
    return r;
}

__global__ __launch_bounds__(256)
void dist_kernel(const float* __restrict__ x,
                 const float* __restrict__ cen,
                 float* __restrict__ out)
{
    // Transposed tiles: [d][row] so the inner loop reads contiguous rows as float4.
    __shared__ float xs[Dn][TM];
    __shared__ float cs[Dn][TN];
    __shared__ float x2s[TM];
    __shared__ float c2s[TN];

    const int g   = blockIdx.z;
    const int b0  = blockIdx.y * TM;
    const int k0  = blockIdx.x * TN;
    const int tid = threadIdx.x;

    // ---- Load tiles (whole D=64 fits; single phase). ----
    // Thread t handles row t%64, d-chunk of 16 starting at (t/64)*16.
    // Shared stores are conflict-free: addr = d*64 + row, lanes cover rows 0..31.
    {
        const int row = tid & 63;
        const int d0  = (tid >> 6) << 4;
        const float* xg = x   + ((size_t)(g * Bn + b0 + row)) * Dn + d0;
        const float* cg = cen + ((size_t)(g * Kn + k0 + row)) * Dn + d0;
#pragma unroll
        for (int i = 0; i < 4; i++) {
            float4 vx = *(const float4*)(xg + 4 * i);
            float4 vc = *(const float4*)(cg + 4 * i);
            const int d = d0 + 4 * i;
            xs[d + 0][row] = vx.x; xs[d + 1][row] = vx.y;
            xs[d + 2][row] = vx.z; xs[d + 3][row] = vx.w;
            cs[d + 0][row] = vc.x; cs[d + 1][row] = vc.y;
            cs[d + 2][row] = vc.z; cs[d + 3][row] = vc.w;
        }
    }
    __syncthreads();

    // ---- Row/col squared norms (once per tile). ----
    if (tid < 128) {
        const int r = tid & 63;
        float s = 0.f;
        if (tid < 64) {
#pragma unroll
            for (int d = 0; d < Dn; d++) s = fmaf(xs[d][r], xs[d][r], s);
            x2s[r] = s;
        } else {
#pragma unroll
            for (int d = 0; d < Dn; d++) s = fmaf(cs[d][r], cs[d][r], s);
            c2s[r] = s;
        }
    }
    __syncthreads();

    // ---- Main loop: 4x4 micro-tile per thread, packed f32x2 FMAs. ----
    const int tx4 = (tid & 15) << 2;   // 4 consecutive centroids
    const int ty4 = (tid >> 4) << 2;   // 4 consecutive x rows

    // acc[i][p] holds the packed pair (dot[i][2p], dot[i][2p+1])
    unsigned long long acc[4][2];
#pragma unroll
    for (int i = 0; i < 4; i++) { acc[i][0] = 0ull; acc[i][1] = 0ull; }

#pragma unroll 16
    for (int d = 0; d < Dn; d++) {
        float4 a = *(const float4*)&xs[d][ty4];
        // Two packed b pairs straight from the float4-aligned shared row.
        ulonglong2 b = *(const ulonglong2*)&cs[d][tx4];

        unsigned long long ap;
        asm("mov.b64 %0, {%1, %1};" : "=l"(ap) : "r"(__float_as_uint(a.x)));
        asm("fma.rn.f32x2 %0, %1, %2, %0;" : "+l"(acc[0][0]) : "l"(ap), "l"(b.x));
        asm("fma.rn.f32x2 %0, %1, %2, %0;" : "+l"(acc[0][1]) : "l"(ap), "l"(b.y));

        asm("mov.b64 %0, {%1, %1};" : "=l"(ap) : "r"(__float_as_uint(a.y)));
        asm("fma.rn.f32x2 %0, %1, %2, %0;" : "+l"(acc[1][0]) : "l"(ap), "l"(b.x));
        asm("fma.rn.f32x2 %0, %1, %2, %0;" : "+l"(acc[1][1]) : "l"(ap), "l"(b.y));

        asm("mov.b64 %0, {%1, %1};" : "=l"(ap) : "r"(__float_as_uint(a.z)));
        asm("fma.rn.f32x2 %0, %1, %2, %0;" : "+l"(acc[2][0]) : "l"(ap), "l"(b.x));
        asm("fma.rn.f32x2 %0, %1, %2, %0;" : "+l"(acc[2][1]) : "l"(ap), "l"(b.y));

        asm("mov.b64 %0, {%1, %1};" : "=l"(ap) : "r"(__float_as_uint(a.w)));
        asm("fma.rn.f32x2 %0, %1, %2, %0;" : "+l"(acc[3][0]) : "l"(ap), "l"(b.x));
        asm("fma.rn.f32x2 %0, %1, %2, %0;" : "+l"(acc[3][1]) : "l"(ap), "l"(b.y));
    }

    // ---- Epilogue: d = sqrt(max(x2 + c2 - 2*dot, 0)), vectorized stores. ----
    float xr[4], cc[4];
#pragma unroll
    for (int i = 0; i < 4; i++) xr[i] = x2s[ty4 + i];
#pragma unroll
    for (int j = 0; j < 4; j++) cc[j] = c2s[tx4 + j];

#pragma unroll
    for (int i = 0; i < 4; i++) {
        float2 p0 = *reinterpret_cast<float2*>(&acc[i][0]);
        float2 p1 = *reinterpret_cast<float2*>(&acc[i][1]);
        float4 o;
        o.x = fsqrt_approx(fmaxf(fmaf(-2.f, p0.x, xr[i] + cc[0]), 0.f));
        o.y = fsqrt_approx(fmaxf(fmaf(-2.f, p0.y, xr[i] + cc[1]), 0.f));
        o.z = fsqrt_approx(fmaxf(fmaf(-2.f, p1.x, xr[i] + cc[2]), 0.f));
        o.w = fsqrt_approx(fmaxf(fmaf(-2.f, p1.y, xr[i] + cc[3]), 0.f));
        float* op = out + ((size_t)(g * Bn + b0 + ty4 + i)) * Kn + (k0 + tx4);
        *(float4*)op = o;
    }
}

extern "C" void kernel_launch(void* const* d_in, const int* in_sizes, int n_in,
                              void* d_out, int out_size)
{
    const float* x   = (const float*)d_in[0];   // [G, B, D] fp32
    const float* cen = (const float*)d_in[1];   // [G, K, D] fp32
    float* out = (float*)d_out;                 // [G, B, K] fp32

    dim3 grid(Kn / TN, Bn / TM, Gn);            // (16, 128, 16) = 32768 CTAs
    dist_kernel<<<grid, 256>>>(x, cen, out);
}

// round 2
// speedup vs baseline: 1.4938x; 1.4938x over previous
#include <cuda_runtime.h>
#include <cstdint>
#include <cstddef>

// Problem constants (fixed by the dataset)
constexpr int Gn = 16;
constexpr int Bn = 8192;
constexpr int Kn = 1024;
constexpr int Dn = 64;

constexpr int TM = 128;   // x rows per CTA
constexpr int TN = 128;   // centroids per CTA
constexpr int DC = 32;    // D-chunk held in smem
constexpr int PAD = 4;    // smem row padding (floats), keeps 16B alignment

// Scratch for precomputed squared norms (device globals: allocation-free).
__device__ float g_x2[Gn * Bn];
__device__ float g_c2[Gn * Kn];

__device__ __forceinline__ float fsqrt_approx(float v) {
    float r;
    asm("sqrt.approx.f32 %0, %1;" : "=f"(r) : "f"(v));
    return r;
}

// ---------------------------------------------------------------------------
// Pass 1: squared norms of every x row and every centroid row.
// ---------------------------------------------------------------------------
__global__ __launch_bounds__(256)
void norms_kernel(const float* __restrict__ x, const float* __restrict__ cen)
{
    const int t  = blockIdx.x * blockDim.x + threadIdx.x;
    const int NX = Gn * Bn;
    const int NC = Gn * Kn;
    if (t < NX) {
        const float4* p = (const float4*)(x + (size_t)t * Dn);
        float s = 0.f;
#pragma unroll
        for (int i = 0; i < Dn / 4; i++) {
            float4 v = p[i];
            s = fmaf(v.x, v.x, s); s = fmaf(v.y, v.y, s);
            s = fmaf(v.z, v.z, s); s = fmaf(v.w, v.w, s);
        }
        g_x2[t] = s;
    } else if (t < NX + NC) {
        const int r = t - NX;
        const float4* p = (const float4*)(cen + (size_t)r * Dn);
        float s = 0.f;
#pragma unroll
        for (int i = 0; i < Dn / 4; i++) {
            float4 v = p[i];
            s = fmaf(v.x, v.x, s); s = fmaf(v.y, v.y, s);
            s = fmaf(v.z, v.z, s); s = fmaf(v.w, v.w, s);
        }
        g_c2[r] = s;
    }
}

// ---------------------------------------------------------------------------
// Pass 2: 128x128 tile per CTA, 8x8 micro-tile per thread, f32x2 FMAs.
// ---------------------------------------------------------------------------
__global__ __launch_bounds__(256, 2)
void dist_kernel(const float* __restrict__ x,
                 const float* __restrict__ cen,
                 float* __restrict__ out)
{
    // Transposed, padded tiles: [d][row]
    __shared__ float xs[DC][TM + PAD];
    __shared__ float cs[DC][TN + PAD];

    const int g   = blockIdx.z;
    const int b0  = blockIdx.y * TM;
    const int k0  = blockIdx.x * TN;
    const int tid = threadIdx.x;

    const int tx8 = (tid & 15) << 3;   // 8 consecutive centroids
    const int ty8 = (tid >> 4) << 3;   // 8 consecutive x rows

    // 8x8 accumulators as 32 packed f32x2 pairs.
    unsigned long long acc[8][4];
#pragma unroll
    for (int i = 0; i < 8; i++)
#pragma unroll
        for (int p = 0; p < 4; p++) acc[i][p] = 0ull;

#pragma unroll
    for (int ch = 0; ch < Dn / DC; ch++) {
        // ---- Load chunk: 128 rows x 32 d, float4 per access, 4 per thread/array.
        {
            const int dbase = ch * DC;
#pragma unroll
            for (int i = 0; i < 4; i++) {
                const int idx  = i * 256 + tid;
                const int row  = idx >> 3;        // 0..127
                const int d    = (idx & 7) << 2;  // 0..28
                float4 vx = *(const float4*)(x   + ((size_t)(g * Bn + b0 + row)) * Dn + dbase + d);
                float4 vc = *(const float4*)(cen + ((size_t)(g * Kn + k0 + row)) * Dn + dbase + d);
                xs[d + 0][row] = vx.x; xs[d + 1][row] = vx.y;
                xs[d + 2][row] = vx.z; xs[d + 3][row] = vx.w;
                cs[d + 0][row] = vc.x; cs[d + 1][row] = vc.y;
                cs[d + 2][row] = vc.z; cs[d + 3][row] = vc.w;
            }
        }
        __syncthreads();

        // ---- 32 d-steps of 8x8 FMAs.
#pragma unroll
        for (int d = 0; d < DC; d++) {
            float4 a0 = *(const float4*)&xs[d][ty8];
            float4 a1 = *(const float4*)&xs[d][ty8 + 4];
            ulonglong2 bA = *(const ulonglong2*)&cs[d][tx8];
            ulonglong2 bB = *(const ulonglong2*)&cs[d][tx8 + 4];

            const float av[8] = {a0.x, a0.y, a0.z, a0.w, a1.x, a1.y, a1.z, a1.w};
#pragma unroll
            for (int i = 0; i < 8; i++) {
                unsigned long long ap;
                asm("mov.b64 %0, {%1, %1};" : "=l"(ap) : "r"(__float_as_uint(av[i])));
                asm("fma.rn.f32x2 %0, %1, %2, %0;" : "+l"(acc[i][0]) : "l"(ap), "l"(bA.x));
                asm("fma.rn.f32x2 %0, %1, %2, %0;" : "+l"(acc[i][1]) : "l"(ap), "l"(bA.y));
                asm("fma.rn.f32x2 %0, %1, %2, %0;" : "+l"(acc[i][2]) : "l"(ap), "l"(bB.x));
                asm("fma.rn.f32x2 %0, %1, %2, %0;" : "+l"(acc[i][3]) : "l"(ap), "l"(bB.y));
            }
        }
        __syncthreads();
    }

    // ---- Epilogue: norms from precomputed scratch, sqrt, vector stores.
    float cv[8];
#pragma unroll
    for (int j = 0; j < 8; j++) cv[j] = g_c2[g * Kn + k0 + tx8 + j];

#pragma unroll
    for (int i = 0; i < 8; i++) {
        const float x2 = g_x2[g * Bn + b0 + ty8 + i];
        float dots[8];
#pragma unroll
        for (int p = 0; p < 4; p++) {
            float2 pr = *reinterpret_cast<float2*>(&acc[i][p]);
            dots[2 * p]     = pr.x;
            dots[2 * p + 1] = pr.y;
        }
        float4 o0, o1;
        o0.x = fsqrt_approx(fmaxf(fmaf(-2.f, dots[0], x2 + cv[0]), 0.f));
        o0.y = fsqrt_approx(fmaxf(fmaf(-2.f, dots[1], x2 + cv[1]), 0.f));
        o0.z = fsqrt_approx(fmaxf(fmaf(-2.f, dots[2], x2 + cv[2]), 0.f));
        o0.w = fsqrt_approx(fmaxf(fmaf(-2.f, dots[3], x2 + cv[3]), 0.f));
        o1.x = fsqrt_approx(fmaxf(fmaf(-2.f, dots[4], x2 + cv[4]), 0.f));
        o1.y = fsqrt_approx(fmaxf(fmaf(-2.f, dots[5], x2 + cv[5]), 0.f));
        o1.z = fsqrt_approx(fmaxf(fmaf(-2.f, dots[6], x2 + cv[6]), 0.f));
        o1.w = fsqrt_approx(fmaxf(fmaf(-2.f, dots[7], x2 + cv[7]), 0.f));
        float* op = out + ((size_t)(g * Bn + b0 + ty8 + i)) * Kn + (k0 + tx8);
        *(float4*)(op)     = o0;
        *(float4*)(op + 4) = o1;
    }
}

extern "C" void kernel_launch(void* const* d_in, const int* in_sizes, int n_in,
                              void* d_out, int out_size)
{
    const float* x   = (const float*)d_in[0];   // [G, B, D] fp32
    const float* cen = (const float*)d_in[1];   // [G, K, D] fp32
    float* out = (float*)d_out;                 // [G, B, K] fp32

    const int nrows = Gn * Bn + Gn * Kn;
    norms_kernel<<<(nrows + 255) / 256, 256>>>(x, cen);

    dim3 grid(Kn / TN, Bn / TM, Gn);            // (8, 64, 16) = 8192 CTAs
    dist_kernel<<<grid, 256>>>(x, cen, out);
}

// round 4
// speedup vs baseline: 3.2238x; 2.1581x over previous
#include <cuda_runtime.h>
#include <cstdint>
#include <cstddef>

// Problem constants (fixed by the dataset)
constexpr int Gn = 16;
constexpr int Bn = 8192;
constexpr int Kn = 1024;
constexpr int Dn = 64;

constexpr int TM = 128;     // x rows per CTA tile
constexpr int TN = 128;     // centroids per CTA tile
constexpr int LDS = 68;     // padded row length (floats): banks (4*row+t4)%32 all distinct

// Precomputed squared norms (device globals: allocation-free scratch).
__device__ float g_x2[Gn * Bn];
__device__ float g_c2[Gn * Kn];

// dynamic smem layout
constexpr int XS_OFF = 0;                       // xs[128][68] tf32 bits
constexpr int CS_OFF = TM * LDS * 4;            // cs[128][68]
constexpr int SMEM_TOTAL = CS_OFF + TN * LDS * 4;   // 69632 B

__device__ __forceinline__ float fsqrt_approx(float v) {
    float r;
    asm("sqrt.approx.f32 %0, %1;" : "=f"(r) : "f"(v));
    return r;
}
__device__ __forceinline__ uint32_t f2tf32(float v) {
    uint32_t r;
    asm("cvt.rna.tf32.f32 %0, %1;" : "=r"(r) : "f"(v));
    return r;
}
__device__ __forceinline__ void mma_tf32(float c[4],
                                         uint32_t a0, uint32_t a1, uint32_t a2, uint32_t a3,
                                         uint32_t b0, uint32_t b1) {
    asm volatile(
        "mma.sync.aligned.m16n8k8.row.col.f32.tf32.tf32.f32 "
        "{%0,%1,%2,%3}, {%4,%5,%6,%7}, {%8,%9}, {%0,%1,%2,%3};"
        : "+f"(c[0]), "+f"(c[1]), "+f"(c[2]), "+f"(c[3])
        : "r"(a0), "r"(a1), "r"(a2), "r"(a3), "r"(b0), "r"(b1));
}

// ---------------------------------------------------------------------------
// Pass 1: squared norms (exact fp32).
// ---------------------------------------------------------------------------
__global__ __launch_bounds__(256)
void norms_kernel(const float* __restrict__ x, const float* __restrict__ cen)
{
    const int t  = blockIdx.x * blockDim.x + threadIdx.x;
    const int NX = Gn * Bn;
    const int NC = Gn * Kn;
    const float4* p;
    if (t < NX)            p = (const float4*)(x   + (size_t)t * Dn);
    else if (t < NX + NC)  p = (const float4*)(cen + (size_t)(t - NX) * Dn);
    else return;
    float s = 0.f;
#pragma unroll
    for (int i = 0; i < Dn / 4; i++) {
        float4 v = p[i];
        s = fmaf(v.x, v.x, s); s = fmaf(v.y, v.y, s);
        s = fmaf(v.z, v.z, s); s = fmaf(v.w, v.w, s);
    }
    if (t < NX) g_x2[t] = s; else g_c2[t - NX] = s;
}

// ---------------------------------------------------------------------------
// Pass 2: 128x128 tile per CTA via tf32 mma.sync (tensor pipe).
//   8 warps in 2(m) x 4(n); warp tile 64x32; k in 8 steps of 8.
// ---------------------------------------------------------------------------
__global__ __launch_bounds__(256, 2)
void dist_kernel(const float* __restrict__ x,
                 const float* __restrict__ cen,
                 float* __restrict__ out)
{
    extern __shared__ __align__(16) uint32_t smem_u[];
    uint32_t* xs = smem_u + XS_OFF / 4;   // [row][k] padded LDS
    uint32_t* cs = smem_u + CS_OFF / 4;

    const int tid  = threadIdx.x;
    const int wid  = tid >> 5;
    const int lane = tid & 31;
    const int qid  = lane >> 2;     // 0..7
    const int t4   = lane & 3;      // 0..3

    const int g  = blockIdx.z;
    const int b0 = blockIdx.y * TM;
    const int k0 = blockIdx.x * TN;

    // ---- Load + convert both tiles (K-major, padded rows). ----
    {
        const float* xg = x   + (size_t)(g * Bn + b0) * Dn;
        const float* cg = cen + (size_t)(g * Kn + k0) * Dn;
#pragma unroll
        for (int i = 0; i < 8; i++) {
            const int idx = i * 256 + tid;       // 0..2047
            const int row = idx >> 4;            // 0..127
            const int k   = (idx & 15) << 2;     // 0..60
            float4 vx = *(const float4*)(xg + row * Dn + k);
            float4 vc = *(const float4*)(cg + row * Dn + k);
            uint4 tx = { f2tf32(vx.x), f2tf32(vx.y), f2tf32(vx.z), f2tf32(vx.w) };
            uint4 tc = { f2tf32(vc.x), f2tf32(vc.y), f2tf32(vc.z), f2tf32(vc.w) };
            *(uint4*)(xs + row * LDS + k) = tx;
            *(uint4*)(cs + row * LDS + k) = tc;
        }
    }
    __syncthreads();

    const int wm = (wid >> 2) * 64;   // warp m-base: 0 / 64
    const int wn = (wid & 3) * 32;    // warp n-base: 0/32/64/96

    // Accumulators: [mt][nt][4]
    float acc[4][4][4];
#pragma unroll
    for (int mt = 0; mt < 4; mt++)
#pragma unroll
        for (int nt = 0; nt < 4; nt++)
#pragma unroll
            for (int r = 0; r < 4; r++) acc[mt][nt][r] = 0.f;

#pragma unroll
    for (int ks = 0; ks < Dn / 8; ks++) {
        const int kb = ks * 8;
        // B fragments: b0 = B[k=t4][n=qid] -> cs[n][k]
        uint32_t bf[4][2];
#pragma unroll
        for (int nt = 0; nt < 4; nt++) {
            const int n = wn + nt * 8 + qid;
            bf[nt][0] = cs[n * LDS + kb + t4];
            bf[nt][1] = cs[n * LDS + kb + t4 + 4];
        }
        // A fragments + MMAs
#pragma unroll
        for (int mt = 0; mt < 4; mt++) {
            const int m = wm + mt * 16 + qid;
            const uint32_t a0 = xs[m * LDS + kb + t4];
            const uint32_t a1 = xs[(m + 8) * LDS + kb + t4];
            const uint32_t a2 = xs[m * LDS + kb + t4 + 4];
            const uint32_t a3 = xs[(m + 8) * LDS + kb + t4 + 4];
#pragma unroll
            for (int nt = 0; nt < 4; nt++)
                mma_tf32(acc[mt][nt], a0, a1, a2, a3, bf[nt][0], bf[nt][1]);
        }
    }

    // ---- Epilogue: d = sqrt(max(x2 + c2 - 2*dot, 0)); float2 stores. ----
    // Thread's output rows: wm+mt*16+qid (c0,c1) and +8 (c2,c3);
    // cols: wn+nt*8+2*t4, +1.
    float c2v[4][2];
#pragma unroll
    for (int nt = 0; nt < 4; nt++) {
        const int n = k0 + wn + nt * 8 + 2 * t4;
        float2 cc = *(const float2*)(g_c2 + g * Kn + n);
        c2v[nt][0] = cc.x; c2v[nt][1] = cc.y;
    }

#pragma unroll
    for (int mt = 0; mt < 4; mt++) {
        const int row0 = b0 + wm + mt * 16 + qid;
        const float x2a = g_x2[g * Bn + row0];
        const float x2b = g_x2[g * Bn + row0 + 8];
        float* opa = out + (size_t)(g * Bn + row0) * Kn + k0 + wn + 2 * t4;
        float* opb = opa + (size_t)8 * Kn;
#pragma unroll
        for (int nt = 0; nt < 4; nt++) {
            float2 oa, ob;
            oa.x = fsqrt_approx(fmaxf(fmaf(-2.f, acc[mt][nt][0], x2a + c2v[nt][0]), 0.f));
            oa.y = fsqrt_approx(fmaxf(fmaf(-2.f, acc[mt][nt][1], x2a + c2v[nt][1]), 0.f));
            ob.x = fsqrt_approx(fmaxf(fmaf(-2.f, acc[mt][nt][2], x2b + c2v[nt][0]), 0.f));
            ob.y = fsqrt_approx(fmaxf(fmaf(-2.f, acc[mt][nt][3], x2b + c2v[nt][1]), 0.f));
            *(float2*)(opa + nt * 8) = oa;
            *(float2*)(opb + nt * 8) = ob;
        }
    }
}

extern "C" void kernel_launch(void* const* d_in, const int* in_sizes, int n_in,
                              void* d_out, int out_size)
{
    const float* x   = (const float*)d_in[0];   // [G, B, D] fp32
    const float* cen = (const float*)d_in[1];   // [G, K, D] fp32
    float* out = (float*)d_out;                 // [G, B, K] fp32

    static bool attr_set = false;
    if (!attr_set) {
        cudaFuncSetAttribute(dist_kernel,
                             cudaFuncAttributeMaxDynamicSharedMemorySize, SMEM_TOTAL);
        attr_set = true;
    }

    const int nrows = Gn * Bn + Gn * Kn;
    norms_kernel<<<(nrows + 255) / 256, 256>>>(x, cen);

    dim3 grid(Kn / TN, Bn / TM, Gn);            // (8, 64, 16) = 8192 CTAs
    dist_kernel<<<grid, 256, SMEM_TOTAL>>>(x, cen, out);
}

// round 5
// speedup vs baseline: 3.6990x; 1.1474x over previous
#include <cuda_runtime.h>
#include <cstdint>
#include <cstddef>

// Problem constants (fixed by the dataset)
constexpr int Gn = 16;
constexpr int Bn = 8192;
constexpr int Kn = 1024;
constexpr int Dn = 64;

constexpr int TM  = 128;   // x rows per tile
constexpr int TN  = 128;   // centroids per CTA (resident)
constexpr int NBT = 4;     // x tiles per CTA

// Precomputed squared norms (device globals: allocation-free scratch).
__device__ float g_x2[Gn * Bn];
__device__ float g_c2[Gn * Kn];

// Dynamic smem (in 4-byte words): cs[8192], xs0[8192], xs1[8192]
constexpr int CS_W  = 0;
constexpr int XS0_W = 8192;
constexpr int XS1_W = 16384;
constexpr int SMEM_TOTAL = 3 * 8192 * 4;   // 98304 B

__device__ __forceinline__ uint32_t smem_u32(const void* p) {
    uint32_t a;
    asm("{ .reg .u64 t; cvta.to.shared.u64 t, %1; cvt.u32.u64 %0, t; }"
        : "=r"(a) : "l"(p));
    return a;
}
__device__ __forceinline__ float fsqrt_approx(float v) {
    float r;
    asm("sqrt.approx.f32 %0, %1;" : "=f"(r) : "f"(v));
    return r;
}
__device__ __forceinline__ void cp16(uint32_t dst, const void* src) {
    asm volatile("cp.async.cg.shared.global [%0], [%1], 16;"
                 :: "r"(dst), "l"(src) : "memory");
}
#define CP_COMMIT() asm volatile("cp.async.commit_group;" ::: "memory")
#define CP_WAIT0()  asm volatile("cp.async.wait_group 0;" ::: "memory")

__device__ __forceinline__ void mma_tf32(float c[4],
                                         uint32_t a0, uint32_t a1, uint32_t a2, uint32_t a3,
                                         uint32_t b0, uint32_t b1) {
    asm volatile(
        "mma.sync.aligned.m16n8k8.row.col.f32.tf32.tf32.f32 "
        "{%0,%1,%2,%3}, {%4,%5,%6,%7}, {%8,%9}, {%0,%1,%2,%3};"
        : "+f"(c[0]), "+f"(c[1]), "+f"(c[2]), "+f"(c[3])
        : "r"(a0), "r"(a1), "r"(a2), "r"(a3), "r"(b0), "r"(b1));
}

// ---------------------------------------------------------------------------
// Pass 1: squared norms (exact fp32).
// ---------------------------------------------------------------------------
__global__ __launch_bounds__(256)
void norms_kernel(const float* __restrict__ x, const float* __restrict__ cen)
{
    const int t  = blockIdx.x * blockDim.x + threadIdx.x;
    const int NX = Gn * Bn;
    const int NC = Gn * Kn;
    const float4* p;
    if (t < NX)            p = (const float4*)(x   + (size_t)t * Dn);
    else if (t < NX + NC)  p = (const float4*)(cen + (size_t)(t - NX) * Dn);
    else return;
    float s = 0.f;
#pragma unroll
    for (int i = 0; i < Dn / 4; i++) {
        float4 v = p[i];
        s = fmaf(v.x, v.x, s); s = fmaf(v.y, v.y, s);
        s = fmaf(v.z, v.z, s); s = fmaf(v.w, v.w, s);
    }
    if (t < NX) g_x2[t] = s; else g_c2[t - NX] = s;
}

// ---------------------------------------------------------------------------
// Pass 2: per CTA: one resident 128-centroid tile x NBT pipelined x-tiles.
//   Smem layout per row: 16 quads (16B), quad position = quad ^ (row & 7).
// ---------------------------------------------------------------------------
__global__ __launch_bounds__(256, 2)
void dist_kernel(const float* __restrict__ x,
                 const float* __restrict__ cen,
                 float* __restrict__ out)
{
    extern __shared__ __align__(128) uint32_t smem[];
    const uint32_t sb = smem_u32(smem);

    const int tid  = threadIdx.x;
    const int wid  = tid >> 5;
    const int lane = tid & 31;
    const int qid  = lane >> 2;     // 0..7
    const int t4   = lane & 3;      // 0..3

    const int g     = blockIdx.z;
    const int k0    = blockIdx.x * TN;
    const int bslab = blockIdx.y * (TM * NBT);

    const float* cg = cen + (size_t)(g * Kn + k0)    * Dn;
    const float* xg = x   + (size_t)(g * Bn + bslab) * Dn;

    // Loader geometry: 2048 quads per tile, 8 per thread.
    const int lrow0  = tid >> 1;            // pairs: thread handles rows tid>>1 + {0,64}? no:
    // simple flat mapping: idx = i*256 + tid; row = idx>>4; quad = idx&15.

    // ---- Prologue: issue c tile, then x tile 0. ----
#pragma unroll
    for (int i = 0; i < 8; i++) {
        const int idx  = i * 256 + tid;
        const int row  = idx >> 4;
        const int quad = idx & 15;
        const uint32_t dst = sb + ((CS_W + row * 64 + ((quad ^ (row & 7)) << 2)) << 2);
        cp16(dst, cg + row * Dn + quad * 4);
    }
    CP_COMMIT();
#pragma unroll
    for (int i = 0; i < 8; i++) {
        const int idx  = i * 256 + tid;
        const int row  = idx >> 4;
        const int quad = idx & 15;
        const uint32_t dst = sb + ((XS0_W + row * 64 + ((quad ^ (row & 7)) << 2)) << 2);
        cp16(dst, xg + row * Dn + quad * 4);
    }
    CP_COMMIT();

    const int wm = (wid >> 2) * 64;   // warp m-base: 0 / 64
    const int wn = (wid & 3) * 32;    // warp n-base: 0/32/64/96

    // Centroid norms: constant across tiles.
    float c2v[4][2];
#pragma unroll
    for (int nt = 0; nt < 4; nt++) {
        float2 cc = *(const float2*)(g_c2 + g * Kn + k0 + wn + nt * 8 + 2 * t4);
        c2v[nt][0] = cc.x; c2v[nt][1] = cc.y;
    }

    const uint32_t* cs = smem + CS_W;

    for (int bt = 0; bt < NBT; bt++) {
        CP_WAIT0();
        __syncthreads();

        // Prefetch next x tile into the other buffer (its previous consumer
        // finished compute before the sync above).
        if (bt + 1 < NBT) {
            const float* xn = xg + (size_t)(bt + 1) * TM * Dn;
            const int base  = ((bt + 1) & 1) ? XS1_W : XS0_W;
#pragma unroll
            for (int i = 0; i < 8; i++) {
                const int idx  = i * 256 + tid;
                const int row  = idx >> 4;
                const int quad = idx & 15;
                const uint32_t dst = sb + ((base + row * 64 + ((quad ^ (row & 7)) << 2)) << 2);
                cp16(dst, xn + row * Dn + quad * 4);
            }
            CP_COMMIT();
        }

        const uint32_t* xs = smem + ((bt & 1) ? XS1_W : XS0_W);

        // ---- MMA mainloop: 8 k-steps of 8. ----
        float acc[4][4][4];
#pragma unroll
        for (int mt = 0; mt < 4; mt++)
#pragma unroll
            for (int nt = 0; nt < 4; nt++)
#pragma unroll
                for (int r = 0; r < 4; r++) acc[mt][nt][r] = 0.f;

#pragma unroll
        for (int ks = 0; ks < Dn / 8; ks++) {
            // Swizzle offsets shared by every fragment this k-step
            // (rows m, m+8 and cols n all have (row&7) == qid).
            const int off0 = (((2 * ks) ^ qid) << 2) + t4;
            const int off1 = off0 ^ 4;

            uint32_t bf[4][2];
#pragma unroll
            for (int nt = 0; nt < 4; nt++) {
                const int n = wn + nt * 8 + qid;
                bf[nt][0] = cs[n * 64 + off0];
                bf[nt][1] = cs[n * 64 + off1];
            }
#pragma unroll
            for (int mt = 0; mt < 4; mt++) {
                const int m = wm + mt * 16 + qid;
                const uint32_t a0 = xs[m * 64 + off0];
                const uint32_t a1 = xs[(m + 8) * 64 + off0];
                const uint32_t a2 = xs[m * 64 + off1];
                const uint32_t a3 = xs[(m + 8) * 64 + off1];
#pragma unroll
                for (int nt = 0; nt < 4; nt++)
                    mma_tf32(acc[mt][nt], a0, a1, a2, a3, bf[nt][0], bf[nt][1]);
            }
        }

        // ---- Epilogue for this tile. ----
        const int b0 = bslab + bt * TM;
#pragma unroll
        for (int mt = 0; mt < 4; mt++) {
            const int row0 = b0 + wm + mt * 16 + qid;
            const float x2a = g_x2[g * Bn + row0];
            const float x2b = g_x2[g * Bn + row0 + 8];
            float* opa = out + (size_t)(g * Bn + row0) * Kn + k0 + wn + 2 * t4;
            float* opb = opa + (size_t)8 * Kn;
#pragma unroll
            for (int nt = 0; nt < 4; nt++) {
                float2 oa, ob;
                oa.x = fsqrt_approx(fmaxf(fmaf(-2.f, acc[mt][nt][0], x2a + c2v[nt][0]), 0.f));
                oa.y = fsqrt_approx(fmaxf(fmaf(-2.f, acc[mt][nt][1], x2a + c2v[nt][1]), 0.f));
                ob.x = fsqrt_approx(fmaxf(fmaf(-2.f, acc[mt][nt][2], x2b + c2v[nt][0]), 0.f));
                ob.y = fsqrt_approx(fmaxf(fmaf(-2.f, acc[mt][nt][3], x2b + c2v[nt][1]), 0.f));
                *(float2*)(opa + nt * 8) = oa;
                *(float2*)(opb + nt * 8) = ob;
            }
        }
    }
}

extern "C" void kernel_launch(void* const* d_in, const int* in_sizes, int n_in,
                              void* d_out, int out_size)
{
    const float* x   = (const float*)d_in[0];   // [G, B, D] fp32
    const float* cen = (const float*)d_in[1];   // [G, K, D] fp32
    float* out = (float*)d_out;                 // [G, B, K] fp32

    static bool attr_set = false;
    if (!attr_set) {
        cudaFuncSetAttribute(dist_kernel,
                             cudaFuncAttributeMaxDynamicSharedMemorySize, SMEM_TOTAL);
        attr_set = true;
    }

    const int nrows = Gn * Bn + Gn * Kn;
    norms_kernel<<<(nrows + 255) / 256, 256>>>(x, cen);

    dim3 grid(Kn / TN, Bn / (TM * NBT), Gn);    // (8, 16, 16) = 2048 CTAs
    dist_kernel<<<grid, 256, SMEM_TOTAL>>>(x, cen, out);
}

// round 6
// speedup vs baseline: 4.6895x; 1.2678x over previous
#include <cuda_runtime.h>
#include <cuda_bf16.h>
#include <cstdint>
#include <cstddef>

// Problem constants (fixed by the dataset)
constexpr int Gn = 16;
constexpr int Bn = 8192;
constexpr int Kn = 1024;
constexpr int Dn = 64;

constexpr int TM  = 128;   // x rows per tile
constexpr int TN  = 128;   // centroids per CTA (resident)
constexpr int NBT = 4;     // x tiles per CTA

// Device-global scratch (allocation-free).
__device__ float g_x2[Gn * Bn];
__device__ float g_c2[Gn * Kn];
__device__ __align__(16) uint32_t g_xb[Gn * Bn * Dn / 2];   // bf16x2 packed
__device__ __align__(16) uint32_t g_cb[Gn * Kn * Dn / 2];

// Dynamic smem (bytes): c tile + 2 x buffers, each 128 rows x 128B (bf16).
constexpr int CS_B  = 0;
constexpr int XS0_B = 16384;
constexpr int XS1_B = 32768;
constexpr int SMEM_TOTAL = 49152;

__device__ __forceinline__ uint32_t smem_u32(const void* p) {
    uint32_t a;
    asm("{ .reg .u64 t; cvta.to.shared.u64 t, %1; cvt.u32.u64 %0, t; }"
        : "=r"(a) : "l"(p));
    return a;
}
__device__ __forceinline__ float fsqrt_approx(float v) {
    float r;
    asm("sqrt.approx.f32 %0, %1;" : "=f"(r) : "f"(v));
    return r;
}
__device__ __forceinline__ uint32_t pack_bf16(float lo, float hi) {
    uint32_t r;
    asm("cvt.rn.bf16x2.f32 %0, %1, %2;" : "=r"(r) : "f"(hi), "f"(lo));
    return r;
}
__device__ __forceinline__ void cp16(uint32_t dst, const void* src) {
    asm volatile("cp.async.cg.shared.global [%0], [%1], 16;"
                 :: "r"(dst), "l"(src) : "memory");
}
#define CP_COMMIT() asm volatile("cp.async.commit_group;" ::: "memory")
#define CP_WAIT0()  asm volatile("cp.async.wait_group 0;" ::: "memory")

__device__ __forceinline__ void ldsm_x4(uint32_t r[4], uint32_t addr) {
    asm volatile("ldmatrix.sync.aligned.m8n8.x4.shared.b16 {%0,%1,%2,%3}, [%4];"
                 : "=r"(r[0]), "=r"(r[1]), "=r"(r[2]), "=r"(r[3]) : "r"(addr));
}
__device__ __forceinline__ void mma_bf16(float c[4], const uint32_t a[4],
                                         uint32_t b0, uint32_t b1) {
    asm volatile(
        "mma.sync.aligned.m16n8k16.row.col.f32.bf16.bf16.f32 "
        "{%0,%1,%2,%3}, {%4,%5,%6,%7}, {%8,%9}, {%0,%1,%2,%3};"
        : "+f"(c[0]), "+f"(c[1]), "+f"(c[2]), "+f"(c[3])
        : "r"(a[0]), "r"(a[1]), "r"(a[2]), "r"(a[3]), "r"(b0), "r"(b1));
}

// ---------------------------------------------------------------------------
// Pass 1: exact fp32 squared norms + bf16 conversion (one row per thread).
// ---------------------------------------------------------------------------
__global__ __launch_bounds__(256)
void prep_kernel(const float* __restrict__ x, const float* __restrict__ cen)
{
    const int t  = blockIdx.x * blockDim.x + threadIdx.x;
    const int NX = Gn * Bn;
    const int NC = Gn * Kn;
    const float4* src;
    uint4* dst;
    if (t < NX) {
        src = (const float4*)(x + (size_t)t * Dn);
        dst = (uint4*)(g_xb + (size_t)t * (Dn / 2));
    } else if (t < NX + NC) {
        src = (const float4*)(cen + (size_t)(t - NX) * Dn);
        dst = (uint4*)(g_cb + (size_t)(t - NX) * (Dn / 2));
    } else return;

    float s = 0.f;
#pragma unroll
    for (int i = 0; i < 8; i++) {
        float4 v0 = src[2 * i];
        float4 v1 = src[2 * i + 1];
        s = fmaf(v0.x, v0.x, s); s = fmaf(v0.y, v0.y, s);
        s = fmaf(v0.z, v0.z, s); s = fmaf(v0.w, v0.w, s);
        s = fmaf(v1.x, v1.x, s); s = fmaf(v1.y, v1.y, s);
        s = fmaf(v1.z, v1.z, s); s = fmaf(v1.w, v1.w, s);
        uint4 o;
        o.x = pack_bf16(v0.x, v0.y); o.y = pack_bf16(v0.z, v0.w);
        o.z = pack_bf16(v1.x, v1.y); o.w = pack_bf16(v1.z, v1.w);
        dst[i] = o;
    }
    if (t < NX) g_x2[t] = s; else g_c2[t - NX] = s;
}

// ---------------------------------------------------------------------------
// Pass 2: resident 128-centroid bf16 tile x NBT pipelined x tiles.
//   Rows are 128B (64 bf16); quad q of row r stored at q ^ (r & 7).
// ---------------------------------------------------------------------------
__global__ __launch_bounds__(256, 2)
void dist_kernel(float* __restrict__ out)
{
    extern __shared__ __align__(128) char smem[];
    const uint32_t sb = smem_u32(smem);

    const int tid  = threadIdx.x;
    const int wid  = tid >> 5;
    const int lane = tid & 31;
    const int qid  = lane >> 2;     // 0..7
    const int t4   = lane & 3;      // 0..3

    const int g     = blockIdx.z;
    const int k0    = blockIdx.x * TN;
    const int bslab = blockIdx.y * (TM * NBT);

    const char* cgb = (const char*)g_cb + (size_t)(g * Kn + k0)    * Dn * 2;
    const char* xgb = (const char*)g_xb + (size_t)(g * Bn + bslab) * Dn * 2;

    // ---- Prologue: c tile, then x tile 0. (1024 16B chunks each; 4/thread)
#pragma unroll
    for (int i = 0; i < 4; i++) {
        const int idx = i * 256 + tid;
        const int row = idx >> 3, q = idx & 7;
        cp16(sb + CS_B + row * 128 + ((q ^ (row & 7)) << 4), cgb + row * 128 + q * 16);
    }
    CP_COMMIT();
#pragma unroll
    for (int i = 0; i < 4; i++) {
        const int idx = i * 256 + tid;
        const int row = idx >> 3, q = idx & 7;
        cp16(sb + XS0_B + row * 128 + ((q ^ (row & 7)) << 4), xgb + row * 128 + q * 16);
    }
    CP_COMMIT();

    const int wm = (wid >> 2) * 64;   // warp m-base: 0 / 64
    const int wn = (wid & 3) * 32;    // warp n-base: 0/32/64/96

    // Centroid norms: constant across tiles.
    float c2v[4][2];
#pragma unroll
    for (int nt = 0; nt < 4; nt++) {
        float2 cc = *(const float2*)(g_c2 + g * Kn + k0 + wn + nt * 8 + 2 * t4);
        c2v[nt][0] = cc.x; c2v[nt][1] = cc.y;
    }

    // Per-lane ldmatrix geometry (row&7 == lane&7 for all our tiles).
    const int swz     = lane & 7;
    const int a_row   = lane & 15;           // + wm + mt*16
    const int a_qoff  = lane >> 4;           // + 2ks
    const int b_nrow  = ((lane >> 4) << 3) + (lane & 7);   // + wn + ntp*16
    const int b_qoff  = (lane >> 3) & 1;     // + 2ks

    for (int bt = 0; bt < NBT; bt++) {
        CP_WAIT0();
        __syncthreads();

        if (bt + 1 < NBT) {
            const char* xn = xgb + (size_t)(bt + 1) * TM * Dn * 2;
            const uint32_t base = sb + (((bt + 1) & 1) ? XS1_B : XS0_B);
#pragma unroll
            for (int i = 0; i < 4; i++) {
                const int idx = i * 256 + tid;
                const int row = idx >> 3, q = idx & 7;
                cp16(base + row * 128 + ((q ^ (row & 7)) << 4), xn + row * 128 + q * 16);
            }
            CP_COMMIT();
        }

        const uint32_t xs_b = sb + ((bt & 1) ? XS1_B : XS0_B);
        const uint32_t cs_b = sb + CS_B;

        // Prefetch this tile's x-row norms (overlaps the MMA mainloop).
        const int b0 = bslab + bt * TM;
        float x2pre[4][2];
#pragma unroll
        for (int mt = 0; mt < 4; mt++) {
            const int row0 = g * Bn + b0 + wm + mt * 16 + qid;
            x2pre[mt][0] = __ldg(g_x2 + row0);
            x2pre[mt][1] = __ldg(g_x2 + row0 + 8);
        }

        float acc[4][4][4];
#pragma unroll
        for (int mt = 0; mt < 4; mt++)
#pragma unroll
            for (int nt = 0; nt < 4; nt++)
#pragma unroll
                for (int r = 0; r < 4; r++) acc[mt][nt][r] = 0.f;

#pragma unroll
        for (int ks = 0; ks < 4; ks++) {
            const uint32_t qa = (uint32_t)(((2 * ks + a_qoff) ^ swz) << 4);
            const uint32_t qb = (uint32_t)(((2 * ks + b_qoff) ^ swz) << 4);

            uint32_t bf[4][2];
            {
                uint32_t r[4];
                ldsm_x4(r, cs_b + (uint32_t)((wn + b_nrow) * 128) + qb);
                bf[0][0] = r[0]; bf[0][1] = r[1]; bf[1][0] = r[2]; bf[1][1] = r[3];
                ldsm_x4(r, cs_b + (uint32_t)((wn + 16 + b_nrow) * 128) + qb);
                bf[2][0] = r[0]; bf[2][1] = r[1]; bf[3][0] = r[2]; bf[3][1] = r[3];
            }
#pragma unroll
            for (int mt = 0; mt < 4; mt++) {
                uint32_t a[4];
                ldsm_x4(a, xs_b + (uint32_t)((wm + mt * 16 + a_row) * 128) + qa);
#pragma unroll
                for (int nt = 0; nt < 4; nt++)
                    mma_bf16(acc[mt][nt], a, bf[nt][0], bf[nt][1]);
            }
        }

        // ---- Epilogue: d = sqrt(max(x2 + c2 - 2*dot, 0)); float2 stores.
#pragma unroll
        for (int mt = 0; mt < 4; mt++) {
            const int row0 = b0 + wm + mt * 16 + qid;
            const float x2a = x2pre[mt][0];
            const float x2b = x2pre[mt][1];
            float* opa = out + (size_t)(g * Bn + row0) * Kn + k0 + wn + 2 * t4;
            float* opb = opa + (size_t)8 * Kn;
#pragma unroll
            for (int nt = 0; nt < 4; nt++) {
                float2 oa, ob;
                oa.x = fsqrt_approx(fmaxf(fmaf(-2.f, acc[mt][nt][0], x2a + c2v[nt][0]), 0.f));
                oa.y = fsqrt_approx(fmaxf(fmaf(-2.f, acc[mt][nt][1], x2a + c2v[nt][1]), 0.f));
                ob.x = fsqrt_approx(fmaxf(fmaf(-2.f, acc[mt][nt][2], x2b + c2v[nt][0]), 0.f));
                ob.y = fsqrt_approx(fmaxf(fmaf(-2.f, acc[mt][nt][3], x2b + c2v[nt][1]), 0.f));
                *(float2*)(opa + nt * 8) = oa;
                *(float2*)(opb + nt * 8) = ob;
            }
        }
    }
}

extern "C" void kernel_launch(void* const* d_in, const int* in_sizes, int n_in,
                              void* d_out, int out_size)
{
    const float* x   = (const float*)d_in[0];   // [G, B, D] fp32
    const float* cen = (const float*)d_in[1];   // [G, K, D] fp32
    float* out = (float*)d_out;                 // [G, B, K] fp32

    static bool attr_set = false;
    if (!attr_set) {
        cudaFuncSetAttribute(dist_kernel,
                             cudaFuncAttributeMaxDynamicSharedMemorySize, SMEM_TOTAL);
        attr_set = true;
    }

    const int nrows = Gn * Bn + Gn * Kn;
    prep_kernel<<<(nrows + 255) / 256, 256>>>(x, cen);

    dim3 grid(Kn / TN, Bn / (TM * NBT), Gn);    // (8, 16, 16) = 2048 CTAs
    dist_kernel<<<grid, 256, SMEM_TOTAL>>>(out);
}

// round 7
// speedup vs baseline: 4.7974x; 1.0230x over previous
#include <cuda_runtime.h>
#include <cuda_bf16.h>
#include <cstdint>
#include <cstddef>

// Problem constants (fixed by the dataset)
constexpr int Gn = 16;
constexpr int Bn = 8192;
constexpr int Kn = 1024;
constexpr int Dn = 64;

constexpr int DP  = 80;    // augmented dim: 64 data + 4 norm terms + 12 zero pad
constexpr int RB  = DP * 2;          // 160 bytes per augmented row
constexpr int TM  = 128;   // x rows per tile
constexpr int TN  = 128;   // centroids per CTA (resident)
constexpr int NBT = 4;     // x tiles per CTA

// Augmented bf16 operands (device globals: allocation-free scratch).
//  x row:  [-2x (64)] [x2_hi, x2_lo, 1, 1] [0 x 12]
//  c row:  [ c  (64)] [1, 1, c2_hi, c2_lo] [0 x 12]
__device__ __align__(16) uint32_t g_xb[(size_t)Gn * Bn * (RB / 4)];
__device__ __align__(16) uint32_t g_cb[(size_t)Gn * Kn * (RB / 4)];

// Dynamic smem layout (bytes). Each tile = 16KB main (128B rows, XOR-swizzled)
// + 4KB aug (32B rows, (2r+q)^((r>>2)&7) swizzle).
constexpr int CS0 = 0;          // c main
constexpr int CS1 = 16384;      // c aug
constexpr int XB0 = 20480;      // x buffer 0: main at +0, aug at +16384
constexpr int XB1 = 40960;      // x buffer 1
constexpr int SMEM_TOTAL = 61440;

__device__ __forceinline__ uint32_t smem_u32(const void* p) {
    uint32_t a;
    asm("{ .reg .u64 t; cvta.to.shared.u64 t, %1; cvt.u32.u64 %0, t; }"
        : "=r"(a) : "l"(p));
    return a;
}
__device__ __forceinline__ float fsqrt_approx(float v) {
    float r;
    asm("sqrt.approx.f32 %0, %1;" : "=f"(r) : "f"(v));
    return r;
}
// packs lo into bits[0:16), hi into bits[16:32)
__device__ __forceinline__ uint32_t pack_bf16(float lo, float hi) {
    uint32_t r;
    asm("cvt.rn.bf16x2.f32 %0, %1, %2;" : "=r"(r) : "f"(hi), "f"(lo));
    return r;
}
__device__ __forceinline__ void cp16(uint32_t dst, const void* src) {
    asm volatile("cp.async.cg.shared.global [%0], [%1], 16;"
                 :: "r"(dst), "l"(src) : "memory");
}
#define CP_COMMIT() asm volatile("cp.async.commit_group;" ::: "memory")
#define CP_WAIT0()  asm volatile("cp.async.wait_group 0;" ::: "memory")

__device__ __forceinline__ void ldsm_x4(uint32_t r[4], uint32_t addr) {
    asm volatile("ldmatrix.sync.aligned.m8n8.x4.shared.b16 {%0,%1,%2,%3}, [%4];"
                 : "=r"(r[0]), "=r"(r[1]), "=r"(r[2]), "=r"(r[3]) : "r"(addr));
}
__device__ __forceinline__ void mma_bf16(float c[4], const uint32_t a[4],
                                         uint32_t b0, uint32_t b1) {
    asm volatile(
        "mma.sync.aligned.m16n8k16.row.col.f32.bf16.bf16.f32 "
        "{%0,%1,%2,%3}, {%4,%5,%6,%7}, {%8,%9}, {%0,%1,%2,%3};"
        : "+f"(c[0]), "+f"(c[1]), "+f"(c[2]), "+f"(c[3])
        : "r"(a[0]), "r"(a[1]), "r"(a[2]), "r"(a[3]), "r"(b0), "r"(b1));
}
// aug-tile address: 32B rows, 16B chunk q of row r lives at flat=(2r+q)^((r>>2)&7)
__device__ __forceinline__ uint32_t t1addr(uint32_t base, int row, int q) {
    return base + (uint32_t)((((row * 2 + q) ^ ((row >> 2) & 7)) << 4));
}

// ---------------------------------------------------------------------------
// Pass 1: build augmented bf16 rows (exact fp32 norms, hi/lo split).
// ---------------------------------------------------------------------------
__global__ __launch_bounds__(256)
void prep_kernel(const float* __restrict__ x, const float* __restrict__ cen)
{
    const int t  = blockIdx.x * blockDim.x + threadIdx.x;
    const int NX = Gn * Bn;
    const int NC = Gn * Kn;
    const float4* src;
    uint4* dst;
    bool is_x;
    if (t < NX) {
        src = (const float4*)(x + (size_t)t * Dn);
        dst = (uint4*)(g_xb + (size_t)t * (RB / 4));
        is_x = true;
    } else if (t < NX + NC) {
        src = (const float4*)(cen + (size_t)(t - NX) * Dn);
        dst = (uint4*)(g_cb + (size_t)(t - NX) * (RB / 4));
        is_x = false;
    } else return;

    const float a = is_x ? -2.0f : 1.0f;
    float s = 0.f;
#pragma unroll
    for (int i = 0; i < 8; i++) {
        float4 v0 = src[2 * i];
        float4 v1 = src[2 * i + 1];
        s = fmaf(v0.x, v0.x, s); s = fmaf(v0.y, v0.y, s);
        s = fmaf(v0.z, v0.z, s); s = fmaf(v0.w, v0.w, s);
        s = fmaf(v1.x, v1.x, s); s = fmaf(v1.y, v1.y, s);
        s = fmaf(v1.z, v1.z, s); s = fmaf(v1.w, v1.w, s);
        uint4 o;
        o.x = pack_bf16(a * v0.x, a * v0.y); o.y = pack_bf16(a * v0.z, a * v0.w);
        o.z = pack_bf16(a * v1.x, a * v1.y); o.w = pack_bf16(a * v1.z, a * v1.w);
        dst[i] = o;
    }
    // hi/lo split of the squared norm
    const float hf  = __bfloat162float(__float2bfloat16(s));
    const float res = s - hf;
    uint4 aug;
    if (is_x) { aug.x = pack_bf16(s, res);   aug.y = pack_bf16(1.f, 1.f); }
    else      { aug.x = pack_bf16(1.f, 1.f); aug.y = pack_bf16(s, res);   }
    aug.z = 0u; aug.w = 0u;
    dst[8] = aug;
    dst[9] = make_uint4(0u, 0u, 0u, 0u);
}

// Tile loader: 1280 16B chunks (128 rows x 160B), 5 per thread.
__device__ __forceinline__ void load_tile(uint32_t t0, uint32_t t1,
                                          const char* gsrc, int tid)
{
#pragma unroll
    for (int i = 0; i < 5; i++) {
        const int idx = i * 256 + tid;
        const int row = idx / 10;
        const int q   = idx - row * 10;
        const char* src = gsrc + row * RB + q * 16;
        if (q < 8) cp16(t0 + row * 128 + ((q ^ (row & 7)) << 4), src);
        else       cp16(t1addr(t1, row, q - 8), src);
    }
}

// ---------------------------------------------------------------------------
// Pass 2: resident 128-centroid tile x NBT pipelined x tiles; acc == d^2.
// ---------------------------------------------------------------------------
__global__ __launch_bounds__(256, 2)
void dist_kernel(float* __restrict__ out)
{
    extern __shared__ __align__(128) char smem[];
    const uint32_t sb = smem_u32(smem);

    const int tid  = threadIdx.x;
    const int wid  = tid >> 5;
    const int lane = tid & 31;
    const int qid  = lane >> 2;     // 0..7
    const int t4   = lane & 3;      // 0..3

    const int g     = blockIdx.z;
    const int k0    = blockIdx.x * TN;
    const int bslab = blockIdx.y * (TM * NBT);

    const char* cgb = (const char*)g_cb + (size_t)(g * Kn + k0)    * RB;
    const char* xgb = (const char*)g_xb + (size_t)(g * Bn + bslab) * RB;

    // ---- Prologue: c tile, then x tile 0. ----
    load_tile(sb + CS0, sb + CS1, cgb, tid);
    CP_COMMIT();
    load_tile(sb + XB0, sb + XB0 + 16384, xgb, tid);
    CP_COMMIT();

    const int wm = (wid >> 2) * 64;   // warp m-base: 0 / 64
    const int wn = (wid & 3) * 32;    // warp n-base: 0/32/64/96

    // Per-lane ldmatrix geometry.
    const int swz    = lane & 7;
    const int a_row  = lane & 15;                        // + wm + mt*16
    const int a_qoff = lane >> 4;                        // 0/1
    const int b_nrow = ((lane >> 4) << 3) + (lane & 7);  // + wn (+16)
    const int b_qoff = (lane >> 3) & 1;                  // 0/1

    for (int bt = 0; bt < NBT; bt++) {
        CP_WAIT0();
        __syncthreads();

        if (bt + 1 < NBT) {
            const char* xn = xgb + (size_t)(bt + 1) * TM * RB;
            const uint32_t base = sb + (((bt + 1) & 1) ? XB1 : XB0);
            load_tile(base, base + 16384, xn, tid);
            CP_COMMIT();
        }

        const uint32_t xs0 = sb + ((bt & 1) ? XB1 : XB0);
        const uint32_t xs1 = xs0 + 16384;
        const uint32_t cs0 = sb + CS0;
        const uint32_t cs1 = sb + CS1;

        float acc[4][4][4];
#pragma unroll
        for (int mt = 0; mt < 4; mt++)
#pragma unroll
            for (int nt = 0; nt < 4; nt++)
#pragma unroll
                for (int r = 0; r < 4; r++) acc[mt][nt][r] = 0.f;

        // ---- k-steps 0..3: main 64 dims (128B swizzled tile). ----
#pragma unroll
        for (int ks = 0; ks < 4; ks++) {
            const uint32_t qa = (uint32_t)(((2 * ks + a_qoff) ^ swz) << 4);
            const uint32_t qb = (uint32_t)(((2 * ks + b_qoff) ^ swz) << 4);

            uint32_t bf[4][2];
            {
                uint32_t r[4];
                ldsm_x4(r, cs0 + (uint32_t)((wn + b_nrow) * 128) + qb);
                bf[0][0] = r[0]; bf[0][1] = r[1]; bf[1][0] = r[2]; bf[1][1] = r[3];
                ldsm_x4(r, cs0 + (uint32_t)((wn + 16 + b_nrow) * 128) + qb);
                bf[2][0] = r[0]; bf[2][1] = r[1]; bf[3][0] = r[2]; bf[3][1] = r[3];
            }
#pragma unroll
            for (int mt = 0; mt < 4; mt++) {
                uint32_t a[4];
                ldsm_x4(a, xs0 + (uint32_t)((wm + mt * 16 + a_row) * 128) + qa);
#pragma unroll
                for (int nt = 0; nt < 4; nt++)
                    mma_bf16(acc[mt][nt], a, bf[nt][0], bf[nt][1]);
            }
        }

        // ---- k-step 4: augmented 16 dims (32B-row tile). ----
        {
            uint32_t bf[4][2];
            {
                uint32_t r[4];
                ldsm_x4(r, t1addr(cs1, wn + b_nrow, b_qoff));
                bf[0][0] = r[0]; bf[0][1] = r[1]; bf[1][0] = r[2]; bf[1][1] = r[3];
                ldsm_x4(r, t1addr(cs1, wn + 16 + b_nrow, b_qoff));
                bf[2][0] = r[0]; bf[2][1] = r[1]; bf[3][0] = r[2]; bf[3][1] = r[3];
            }
#pragma unroll
            for (int mt = 0; mt < 4; mt++) {
                uint32_t a[4];
                ldsm_x4(a, t1addr(xs1, wm + mt * 16 + a_row, a_qoff));
#pragma unroll
                for (int nt = 0; nt < 4; nt++)
                    mma_bf16(acc[mt][nt], a, bf[nt][0], bf[nt][1]);
            }
        }

        // ---- Epilogue: acc IS d^2 -> sqrt + store. ----
        const int b0 = bslab + bt * TM;
#pragma unroll
        for (int mt = 0; mt < 4; mt++) {
            const int row0 = b0 + wm + mt * 16 + qid;
            float* opa = out + (size_t)(g * Bn + row0) * Kn + k0 + wn + 2 * t4;
            float* opb = opa + (size_t)8 * Kn;
#pragma unroll
            for (int nt = 0; nt < 4; nt++) {
                float2 oa, ob;
                oa.x = fsqrt_approx(acc[mt][nt][0]);
                oa.y = fsqrt_approx(acc[mt][nt][1]);
                ob.x = fsqrt_approx(acc[mt][nt][2]);
                ob.y = fsqrt_approx(acc[mt][nt][3]);
                *(float2*)(opa + nt * 8) = oa;
                *(float2*)(opb + nt * 8) = ob;
            }
        }
    }
}

extern "C" void kernel_launch(void* const* d_in, const int* in_sizes, int n_in,
                              void* d_out, int out_size)
{
    const float* x   = (const float*)d_in[0];   // [G, B, D] fp32
    const float* cen = (const float*)d_in[1];   // [G, K, D] fp32
    float* out = (float*)d_out;                 // [G, B, K] fp32

    static bool attr_set = false;
    if (!attr_set) {
        cudaFuncSetAttribute(dist_kernel,
                             cudaFuncAttributeMaxDynamicSharedMemorySize, SMEM_TOTAL);
        attr_set = true;
    }

    const int nrows = Gn * Bn + Gn * Kn;
    prep_kernel<<<(nrows + 255) / 256, 256>>>(x, cen);

    dim3 grid(Kn / TN, Bn / (TM * NBT), Gn);    // (8, 16, 16) = 2048 CTAs
    dist_kernel<<<grid, 256, SMEM_TOTAL>>>(out);
}

// round 8
// speedup vs baseline: 4.8597x; 1.0130x over previous
#include <cuda_runtime.h>
#include <cuda_fp16.h>
#include <cstdint>
#include <cstddef>
#include <cstring>

// Problem constants (fixed by the dataset)
constexpr int Gn = 16;
constexpr int Bn = 8192;
constexpr int Kn = 1024;
constexpr int Dn = 64;

constexpr int DP  = 80;              // augmented dim: 64 data + 4 norm + 12 pad
constexpr int RB  = DP * 2;          // 160 bytes per augmented row
constexpr int TM  = 128;             // x rows per tile
constexpr int TN  = 128;             // centroids per CTA (resident)
constexpr int NBT = 4;               // x tiles per CTA
constexpr int NT  = 512;             // threads per CTA

// Augmented f16 operands (device globals: allocation-free scratch).
//  x row:  [-2x (64)] [x2_hi, x2_lo, 1, 1] [0 x 12]
//  c row:  [ c  (64)] [1, 1, c2_hi, c2_lo] [0 x 12]
__device__ __align__(16) uint32_t g_xb[(size_t)Gn * Bn * (RB / 4)];
__device__ __align__(16) uint32_t g_cb[(size_t)Gn * Kn * (RB / 4)];

// Dynamic smem layout (bytes): 16KB main (128B rows, XOR swizzle) + 4KB aug
// (32B rows, (2r+q)^((r>>2)&7) swizzle) per tile.
constexpr int CS0 = 0;          // c main
constexpr int CS1 = 16384;      // c aug
constexpr int XB0 = 20480;      // x buffer 0
constexpr int XB1 = 40960;      // x buffer 1
constexpr int SMEM_TOTAL = 61440;

__device__ __forceinline__ uint32_t smem_u32(const void* p) {
    uint32_t a;
    asm("{ .reg .u64 t; cvta.to.shared.u64 t, %1; cvt.u32.u64 %0, t; }"
        : "=r"(a) : "l"(p));
    return a;
}
__device__ __forceinline__ float fsqrt_approx(float v) {
    float r;
    asm("sqrt.approx.f32 %0, %1;" : "=f"(r) : "f"(v));
    return r;
}
__device__ __forceinline__ uint32_t pack_f16(float lo, float hi) {
    __half2 h = __floats2half2_rn(lo, hi);   // .x = lo (low half)
    uint32_t u;
    memcpy(&u, &h, 4);
    return u;
}
__device__ __forceinline__ void cp16(uint32_t dst, const void* src) {
    asm volatile("cp.async.cg.shared.global [%0], [%1], 16;"
                 :: "r"(dst), "l"(src) : "memory");
}
#define CP_COMMIT() asm volatile("cp.async.commit_group;" ::: "memory")
#define CP_WAIT0()  asm volatile("cp.async.wait_group 0;" ::: "memory")

__device__ __forceinline__ void ldsm_x4(uint32_t r[4], uint32_t addr) {
    asm volatile("ldmatrix.sync.aligned.m8n8.x4.shared.b16 {%0,%1,%2,%3}, [%4];"
                 : "=r"(r[0]), "=r"(r[1]), "=r"(r[2]), "=r"(r[3]) : "r"(addr));
}
// f16 x f16 -> f16 accumulate: D/C in 2 regs (f16x2 each)
__device__ __forceinline__ void mma_f16(uint32_t c[2], const uint32_t a[4],
                                        uint32_t b0, uint32_t b1) {
    asm volatile(
        "mma.sync.aligned.m16n8k16.row.col.f16.f16.f16.f16 "
        "{%0,%1}, {%2,%3,%4,%5}, {%6,%7}, {%0,%1};"
        : "+r"(c[0]), "+r"(c[1])
        : "r"(a[0]), "r"(a[1]), "r"(a[2]), "r"(a[3]), "r"(b0), "r"(b1));
}
__device__ __forceinline__ void stg_cs2(float* p, float a, float b) {
    asm volatile("st.global.cs.v2.f32 [%0], {%1, %2};"
                 :: "l"(p), "f"(a), "f"(b) : "memory");
}
// aug-tile address: 32B rows; 16B chunk q of row r at flat=(2r+q)^((r>>2)&7)
__device__ __forceinline__ uint32_t t1addr(uint32_t base, int row, int q) {
    return base + (uint32_t)((((row * 2 + q) ^ ((row >> 2) & 7)) << 4));
}

// ---------------------------------------------------------------------------
// Pass 1: build augmented f16 rows (exact fp32 norms, f16 hi/lo split).
// ---------------------------------------------------------------------------
__global__ __launch_bounds__(256)
void prep_kernel(const float* __restrict__ x, const float* __restrict__ cen)
{
    const int t  = blockIdx.x * blockDim.x + threadIdx.x;
    const int NX = Gn * Bn;
    const int NC = Gn * Kn;
    const float4* src;
    uint4* dst;
    bool is_x;
    if (t < NX) {
        src = (const float4*)(x + (size_t)t * Dn);
        dst = (uint4*)(g_xb + (size_t)t * (RB / 4));
        is_x = true;
    } else if (t < NX + NC) {
        src = (const float4*)(cen + (size_t)(t - NX) * Dn);
        dst = (uint4*)(g_cb + (size_t)(t - NX) * (RB / 4));
        is_x = false;
    } else return;

    const float a = is_x ? -2.0f : 1.0f;
    float s = 0.f;
#pragma unroll
    for (int i = 0; i < 8; i++) {
        float4 v0 = src[2 * i];
        float4 v1 = src[2 * i + 1];
        s = fmaf(v0.x, v0.x, s); s = fmaf(v0.y, v0.y, s);
        s = fmaf(v0.z, v0.z, s); s = fmaf(v0.w, v0.w, s);
        s = fmaf(v1.x, v1.x, s); s = fmaf(v1.y, v1.y, s);
        s = fmaf(v1.z, v1.z, s); s = fmaf(v1.w, v1.w, s);
        uint4 o;
        o.x = pack_f16(a * v0.x, a * v0.y); o.y = pack_f16(a * v0.z, a * v0.w);
        o.z = pack_f16(a * v1.x, a * v1.y); o.w = pack_f16(a * v1.z, a * v1.w);
        dst[i] = o;
    }
    // f16 hi/lo split of the squared norm
    const float hf  = __half2float(__float2half_rn(s));
    const float res = s - hf;
    uint4 aug;
    if (is_x) { aug.x = pack_f16(hf, res);   aug.y = pack_f16(1.f, 1.f); }
    else      { aug.x = pack_f16(1.f, 1.f);  aug.y = pack_f16(hf, res);  }
    aug.z = 0u; aug.w = 0u;
    dst[8] = aug;
    dst[9] = make_uint4(0u, 0u, 0u, 0u);
}

// Tile loader: 1280 16B chunks (128 rows x 160B) over 512 threads.
__device__ __forceinline__ void load_tile(uint32_t t0, uint32_t t1,
                                          const char* gsrc, int tid)
{
#pragma unroll
    for (int i = 0; i < 3; i++) {
        const int idx = i * NT + tid;
        if (idx < 1280) {
            const int row = idx / 10;
            const int q   = idx - row * 10;
            const char* src = gsrc + row * RB + q * 16;
            if (q < 8) cp16(t0 + row * 128 + ((q ^ (row & 7)) << 4), src);
            else       cp16(t1addr(t1, row, q - 8), src);
        }
    }
}

// ---------------------------------------------------------------------------
// Pass 2: 512 threads, 4x4 warps of 32x32 tiles; f16 acc == d^2.
// ---------------------------------------------------------------------------
__global__ __launch_bounds__(NT, 2)
void dist_kernel(float* __restrict__ out)
{
    extern __shared__ __align__(128) char smem[];
    const uint32_t sb = smem_u32(smem);

    const int tid  = threadIdx.x;
    const int wid  = tid >> 5;
    const int lane = tid & 31;
    const int qid  = lane >> 2;     // 0..7
    const int t4   = lane & 3;      // 0..3

    const int g     = blockIdx.z;
    const int k0    = blockIdx.x * TN;
    const int bslab = blockIdx.y * (TM * NBT);

    const char* cgb = (const char*)g_cb + (size_t)(g * Kn + k0)    * RB;
    const char* xgb = (const char*)g_xb + (size_t)(g * Bn + bslab) * RB;

    // ---- Prologue: c tile, then x tile 0. ----
    load_tile(sb + CS0, sb + CS1, cgb, tid);
    CP_COMMIT();
    load_tile(sb + XB0, sb + XB0 + 16384, xgb, tid);
    CP_COMMIT();

    const int wm = (wid >> 2) * 32;   // warp m-base: 0/32/64/96
    const int wn = (wid & 3) * 32;    // warp n-base: 0/32/64/96

    // Per-lane ldmatrix geometry.
    const int swz    = lane & 7;
    const int a_row  = lane & 15;                        // + wm + mt*16
    const int a_qoff = lane >> 4;                        // 0/1
    const int b_nrow = ((lane >> 4) << 3) + (lane & 7);  // + wn (+16)
    const int b_qoff = (lane >> 3) & 1;                  // 0/1

    for (int bt = 0; bt < NBT; bt++) {
        CP_WAIT0();
        __syncthreads();

        if (bt + 1 < NBT) {
            const char* xn = xgb + (size_t)(bt + 1) * TM * RB;
            const uint32_t base = sb + (((bt + 1) & 1) ? XB1 : XB0);
            load_tile(base, base + 16384, xn, tid);
            CP_COMMIT();
        }

        const uint32_t xs0 = sb + ((bt & 1) ? XB1 : XB0);
        const uint32_t xs1 = xs0 + 16384;
        const uint32_t cs0 = sb + CS0;
        const uint32_t cs1 = sb + CS1;

        // acc[mt][nt][2]: f16x2 pairs; ends up holding d^2.
        uint32_t acc[2][4][2];
#pragma unroll
        for (int mt = 0; mt < 2; mt++)
#pragma unroll
            for (int nt = 0; nt < 4; nt++) { acc[mt][nt][0] = 0u; acc[mt][nt][1] = 0u; }

        // ---- k-steps 0..3: main 64 dims. ----
#pragma unroll
        for (int ks = 0; ks < 4; ks++) {
            const uint32_t qa = (uint32_t)(((2 * ks + a_qoff) ^ swz) << 4);
            const uint32_t qb = (uint32_t)(((2 * ks + b_qoff) ^ swz) << 4);

            uint32_t bf[4][2];
            {
                uint32_t r[4];
                ldsm_x4(r, cs0 + (uint32_t)((wn + b_nrow) * 128) + qb);
                bf[0][0] = r[0]; bf[0][1] = r[1]; bf[1][0] = r[2]; bf[1][1] = r[3];
                ldsm_x4(r, cs0 + (uint32_t)((wn + 16 + b_nrow) * 128) + qb);
                bf[2][0] = r[0]; bf[2][1] = r[1]; bf[3][0] = r[2]; bf[3][1] = r[3];
            }
#pragma unroll
            for (int mt = 0; mt < 2; mt++) {
                uint32_t a[4];
                ldsm_x4(a, xs0 + (uint32_t)((wm + mt * 16 + a_row) * 128) + qa);
#pragma unroll
                for (int nt = 0; nt < 4; nt++)
                    mma_f16(acc[mt][nt], a, bf[nt][0], bf[nt][1]);
            }
        }

        // ---- k-step 4: augmented 16 dims. ----
        {
            uint32_t bf[4][2];
            {
                uint32_t r[4];
                ldsm_x4(r, t1addr(cs1, wn + b_nrow, b_qoff));
                bf[0][0] = r[0]; bf[0][1] = r[1]; bf[1][0] = r[2]; bf[1][1] = r[3];
                ldsm_x4(r, t1addr(cs1, wn + 16 + b_nrow, b_qoff));
                bf[2][0] = r[0]; bf[2][1] = r[1]; bf[3][0] = r[2]; bf[3][1] = r[3];
            }
#pragma unroll
            for (int mt = 0; mt < 2; mt++) {
                uint32_t a[4];
                ldsm_x4(a, t1addr(xs1, wm + mt * 16 + a_row, a_qoff));
#pragma unroll
                for (int nt = 0; nt < 4; nt++)
                    mma_f16(acc[mt][nt], a, bf[nt][0], bf[nt][1]);
            }
        }

        // ---- Epilogue: unpack f16 d^2 -> sqrt -> streaming store. ----
        const int b0 = bslab + bt * TM;
#pragma unroll
        for (int mt = 0; mt < 2; mt++) {
            const int row0 = b0 + wm + mt * 16 + qid;
            float* opa = out + (size_t)(g * Bn + row0) * Kn + k0 + wn + 2 * t4;
            float* opb = opa + (size_t)8 * Kn;
#pragma unroll
            for (int nt = 0; nt < 4; nt++) {
                __half2 h0, h1;
                memcpy(&h0, &acc[mt][nt][0], 4);
                memcpy(&h1, &acc[mt][nt][1], 4);
                float2 f0 = __half22float2(h0);   // row0:  cols 2t4, 2t4+1
                float2 f1 = __half22float2(h1);   // row0+8
                stg_cs2(opa + nt * 8, fsqrt_approx(f0.x), fsqrt_approx(f0.y));
                stg_cs2(opb + nt * 8, fsqrt_approx(f1.x), fsqrt_approx(f1.y));
            }
        }
    }
}

extern "C" void kernel_launch(void* const* d_in, const int* in_sizes, int n_in,
                              void* d_out, int out_size)
{
    const float* x   = (const float*)d_in[0];   // [G, B, D] fp32
    const float* cen = (const float*)d_in[1];   // [G, K, D] fp32
    float* out = (float*)d_out;                 // [G, B, K] fp32

    static bool attr_set = false;
    if (!attr_set) {
        cudaFuncSetAttribute(dist_kernel,
                             cudaFuncAttributeMaxDynamicSharedMemorySize, SMEM_TOTAL);
        attr_set = true;
    }

    const int nrows = Gn * Bn + Gn * Kn;
    prep_kernel<<<(nrows + 255) / 256, 256>>>(x, cen);

    dim3 grid(Kn / TN, Bn / (TM * NBT), Gn);    // (8, 16, 16) = 2048 CTAs
    dist_kernel<<<grid, NT, SMEM_TOTAL>>>(out);
}